// round 6
// baseline (speedup 1.0000x reference)
#include <cuda_runtime.h>

#define SEQ    8192
#define NH     32
#define NKV    8
#define HD     128
#define QSIZE  (NH * HD)            // 4096
#define KVSIZE (NKV * HD)           // 1024
#define ROW    (QSIZE + 2 * KVSIZE) // 6144
#define EPSV   1e-6f

#define WARPS_PER_BLOCK 8
#define THREADS 256
#define ROWS_PER_WARP 4

// QK rows: SEQ*(NH+NKV)=327680. 4 rows per warp -> 81920 warp-tasks -> /8 = 10240 blocks
#define QK_TASKS  ((SEQ * (NH + NKV)) / ROWS_PER_WARP)
#define QK_BLOCKS (QK_TASKS / WARPS_PER_BLOCK)
// V copy: SEQ*KVSIZE/4 float4 = 2097152; 4 per thread -> /1024 = 2048 blocks
#define V_FLOAT4  ((SEQ * KVSIZE) / 4)
#define V_BLOCKS  (V_FLOAT4 / (THREADS * 4))

__device__ __forceinline__ void row_ptrs(int row, const float* qkv, float* out,
                                         const float* qw, const float* kw,
                                         const float*& src, float*& dst, const float*& w)
{
    const int s = row / (NH + NKV);
    const int h = row - s * (NH + NKV);
    if (h < NH) {
        src = qkv + (size_t)s * ROW + h * HD;
        dst = out + (size_t)s * QSIZE + h * HD;
        w   = qw;
    } else {
        const int kh = h - NH;
        src = qkv + (size_t)s * ROW + QSIZE + kh * HD;
        dst = out + (size_t)SEQ * QSIZE + (size_t)s * KVSIZE + kh * HD;
        w   = kw;
    }
}

__global__ __launch_bounds__(THREADS)
void qknorm_rope_kernel(const float* __restrict__ qkv,
                        const float* __restrict__ qw,
                        const float* __restrict__ kw,
                        const float* __restrict__ cosw,
                        const float* __restrict__ sinw,
                        float* __restrict__ out)
{
    if (blockIdx.x < QK_BLOCKS) {
        const int warp = threadIdx.x >> 5;
        const int lane = threadIdx.x & 31;
        const int task = blockIdx.x * WARPS_PER_BLOCK + warp;
        const int row0 = task * ROWS_PER_WARP;
        const int d0 = lane * 4;

        const float* src[ROWS_PER_WARP];
        float*       dst[ROWS_PER_WARP];
        const float* w[ROWS_PER_WARP];
        #pragma unroll
        for (int r = 0; r < ROWS_PER_WARP; r++)
            row_ptrs(row0 + r, qkv, out, qw, kw, src[r], dst[r], w[r]);

        // 4 independent 16B loads issued back-to-back (MLP_p1=4), streaming.
        float4 x[ROWS_PER_WARP];
        #pragma unroll
        for (int r = 0; r < ROWS_PER_WARP; r++)
            x[r] = __ldcs(reinterpret_cast<const float4*>(src[r] + d0));

        float ss[ROWS_PER_WARP];
        #pragma unroll
        for (int r = 0; r < ROWS_PER_WARP; r++)
            ss[r] = x[r].x * x[r].x + x[r].y * x[r].y
                  + x[r].z * x[r].z + x[r].w * x[r].w;

        // 4-way interleaved butterfly reductions: SHFL latency fully pipelined.
        #pragma unroll
        for (int off = 16; off > 0; off >>= 1) {
            #pragma unroll
            for (int r = 0; r < ROWS_PER_WARP; r++)
                ss[r] += __shfl_xor_sync(0xffffffffu, ss[r], off);
        }

        float inv[ROWS_PER_WARP];
        #pragma unroll
        for (int r = 0; r < ROWS_PER_WARP; r++)
            inv[r] = rsqrtf(ss[r] * (1.0f / HD) + EPSV);

        float4 cv = *reinterpret_cast<const float4*>(cosw + d0);
        float4 sv = *reinterpret_cast<const float4*>(sinw + d0);
        const float sign = (lane < 16) ? -1.0f : 1.0f;

        // Normalized values per row.
        float n[ROWS_PER_WARP][4];
        #pragma unroll
        for (int r = 0; r < ROWS_PER_WARP; r++) {
            float4 wv = *reinterpret_cast<const float4*>(w[r] + d0);
            n[r][0] = x[r].x * inv[r] * wv.x;
            n[r][1] = x[r].y * inv[r] * wv.y;
            n[r][2] = x[r].z * inv[r] * wv.z;
            n[r][3] = x[r].w * inv[r] * wv.w;
        }

        // Partner exchange (lane^16, same slot), interleaved across rows.
        float p[ROWS_PER_WARP][4];
        #pragma unroll
        for (int j = 0; j < 4; j++) {
            #pragma unroll
            for (int r = 0; r < ROWS_PER_WARP; r++)
                p[r][j] = __shfl_xor_sync(0xffffffffu, n[r][j], 16);
        }

        #pragma unroll
        for (int r = 0; r < ROWS_PER_WARP; r++) {
            float4 o;
            o.x = n[r][0] * cv.x + sign * p[r][0] * sv.x;
            o.y = n[r][1] * cv.y + sign * p[r][1] * sv.y;
            o.z = n[r][2] * cv.z + sign * p[r][2] * sv.z;
            o.w = n[r][3] * cv.w + sign * p[r][3] * sv.w;
            __stcs(reinterpret_cast<float4*>(dst[r] + d0), o);
        }
    } else {
        // V passthrough: 4 float4 per thread (MLP=4), streaming hints.
        const int vblock = blockIdx.x - QK_BLOCKS;
        const float* vbase = qkv + QSIZE + KVSIZE;
        float* vout = out + (size_t)SEQ * (QSIZE + KVSIZE);

        int idx[4];
        float4 v[4];
        #pragma unroll
        for (int u = 0; u < 4; u++)
            idx[u] = vblock * (THREADS * 4) + u * THREADS + threadIdx.x;
        #pragma unroll
        for (int u = 0; u < 4; u++) {
            const int s = idx[u] >> 8;         // 256 float4 per row
            const int c = idx[u] & 255;
            v[u] = __ldcs(reinterpret_cast<const float4*>(vbase + (size_t)s * ROW) + c);
        }
        #pragma unroll
        for (int u = 0; u < 4; u++)
            __stcs(reinterpret_cast<float4*>(vout) + idx[u], v[u]);
    }
}

extern "C" void kernel_launch(void* const* d_in, const int* in_sizes, int n_in,
                              void* d_out, int out_size)
{
    const float* qkv  = (const float*)d_in[0];
    const float* qw   = (const float*)d_in[1];
    const float* kw   = (const float*)d_in[2];
    const float* cosw = (const float*)d_in[3];
    const float* sinw = (const float*)d_in[4];
    float* out = (float*)d_out;

    qknorm_rope_kernel<<<QK_BLOCKS + V_BLOCKS, THREADS>>>(qkv, qw, kw, cosw, sinw, out);
}

// round 7
// speedup vs baseline: 1.0379x; 1.0379x over previous
#include <cuda_runtime.h>

#define SEQ    8192
#define NH     32
#define NKV    8
#define NHT    (NH + NKV)           // 40 heads total per token
#define HD     128
#define HALF   (HD / 2)             // 64
#define QSIZE  (NH * HD)            // 4096
#define KVSIZE (NKV * HD)           // 1024
#define ROW    (QSIZE + 2 * KVSIZE) // 6144
#define EPSV   1e-6f

#define WARPS_PER_BLOCK 8
#define THREADS 256

// Each warp handles 2 head-rows (lanes 0-15 -> row A, lanes 16-31 -> row B).
#define QK_TASKS  ((SEQ * NHT) / 2)            // 163840
#define QK_BLOCKS (QK_TASKS / WARPS_PER_BLOCK) // 20480
// V copy: SEQ*KVSIZE/4 float4 = 2097152; 2 per thread -> /512 = 4096 blocks
#define V_FLOAT4  ((SEQ * KVSIZE) / 4)
#define V_BLOCKS  (V_FLOAT4 / (THREADS * 2))

__global__ __launch_bounds__(THREADS)
void qknorm_rope_kernel(const float* __restrict__ qkv,
                        const float* __restrict__ qw,
                        const float* __restrict__ kw,
                        const float* __restrict__ cosw,
                        const float* __restrict__ sinw,
                        float* __restrict__ out)
{
    if (blockIdx.x < QK_BLOCKS) {
        const int warp = threadIdx.x >> 5;
        const int lane = threadIdx.x & 31;
        const int task = blockIdx.x * WARPS_PER_BLOCK + warp;
        // Lane's own row: lanes 0-15 -> even row, 16-31 -> odd row.
        const int row = task * 2 + (lane >> 4);
        const int c   = (lane & 15) * 4;        // column 0..60 within lo half

        const int s = row / NHT;
        const int h = row - s * NHT;

        const float* __restrict__ src;
        float*       __restrict__ dst;
        const float* __restrict__ w;
        if (h < NH) {
            src = qkv + (size_t)s * ROW + h * HD;
            dst = out + (size_t)s * QSIZE + h * HD;
            w   = qw;
        } else {
            const int kh = h - NH;
            src = qkv + (size_t)s * ROW + QSIZE + kh * HD;
            dst = out + (size_t)SEQ * QSIZE + (size_t)s * KVSIZE + kh * HD;
            w   = kw;
        }

        // Each lane owns a rotate_half pair: [c, c+4) and [c+64, c+68).
        // Two independent streaming loads back-to-back (MLP_p1 = 2).
        float4 xlo = __ldcs(reinterpret_cast<const float4*>(src + c));
        float4 xhi = __ldcs(reinterpret_cast<const float4*>(src + c + HALF));

        float ss = xlo.x * xlo.x + xlo.y * xlo.y + xlo.z * xlo.z + xlo.w * xlo.w
                 + xhi.x * xhi.x + xhi.y * xhi.y + xhi.z * xhi.z + xhi.w * xhi.w;

        // Reduce over each 16-lane half-warp: both rows reduce in ONE 4-step chain.
        #pragma unroll
        for (int off = 8; off > 0; off >>= 1)
            ss += __shfl_xor_sync(0xffffffffu, ss, off);

        const float inv = rsqrtf(ss * (1.0f / HD) + EPSV);

        float4 wlo = *reinterpret_cast<const float4*>(w    + c);
        float4 whi = *reinterpret_cast<const float4*>(w    + c + HALF);
        float4 clo = *reinterpret_cast<const float4*>(cosw + c);
        float4 chi = *reinterpret_cast<const float4*>(cosw + c + HALF);
        float4 slo = *reinterpret_cast<const float4*>(sinw + c);
        float4 shi = *reinterpret_cast<const float4*>(sinw + c + HALF);

        const float nl0 = xlo.x * inv * wlo.x, nl1 = xlo.y * inv * wlo.y;
        const float nl2 = xlo.z * inv * wlo.z, nl3 = xlo.w * inv * wlo.w;
        const float nh0 = xhi.x * inv * whi.x, nh1 = xhi.y * inv * whi.y;
        const float nh2 = xhi.z * inv * whi.z, nh3 = xhi.w * inv * whi.w;

        // rotate_half in-register: out_lo = n_lo*cos_lo - n_hi*sin_lo
        //                          out_hi = n_hi*cos_hi + n_lo*sin_hi
        float4 olo, ohi;
        olo.x = nl0 * clo.x - nh0 * slo.x;
        olo.y = nl1 * clo.y - nh1 * slo.y;
        olo.z = nl2 * clo.z - nh2 * slo.z;
        olo.w = nl3 * clo.w - nh3 * slo.w;
        ohi.x = nh0 * chi.x + nl0 * shi.x;
        ohi.y = nh1 * chi.y + nl1 * shi.y;
        ohi.z = nh2 * chi.z + nl2 * shi.z;
        ohi.w = nh3 * chi.w + nl3 * shi.w;

        __stcs(reinterpret_cast<float4*>(dst + c), olo);
        __stcs(reinterpret_cast<float4*>(dst + c + HALF), ohi);
    } else {
        // V passthrough: 2 float4 per thread, streaming hints.
        const int vblock = blockIdx.x - QK_BLOCKS;
        const int i0 = vblock * (THREADS * 2) + threadIdx.x;
        const int i1 = i0 + THREADS;
        const float* vbase = qkv + QSIZE + KVSIZE;
        float* vout = out + (size_t)SEQ * (QSIZE + KVSIZE);

        const int s0 = i0 >> 8, c0 = i0 & 255;   // 256 float4 per row
        const int s1 = i1 >> 8, c1 = i1 & 255;

        float4 v0 = __ldcs(reinterpret_cast<const float4*>(vbase + (size_t)s0 * ROW) + c0);
        float4 v1 = __ldcs(reinterpret_cast<const float4*>(vbase + (size_t)s1 * ROW) + c1);
        __stcs(reinterpret_cast<float4*>(vout) + i0, v0);
        __stcs(reinterpret_cast<float4*>(vout) + i1, v1);
    }
}

extern "C" void kernel_launch(void* const* d_in, const int* in_sizes, int n_in,
                              void* d_out, int out_size)
{
    const float* qkv  = (const float*)d_in[0];
    const float* qw   = (const float*)d_in[1];
    const float* kw   = (const float*)d_in[2];
    const float* cosw = (const float*)d_in[3];
    const float* sinw = (const float*)d_in[4];
    float* out = (float*)d_out;

    qknorm_rope_kernel<<<QK_BLOCKS + V_BLOCKS, THREADS>>>(qkv, qw, kw, cosw, sinw, out);
}